// round 5
// baseline (speedup 1.0000x reference)
#include <cuda_runtime.h>

#define BZ   32
#define CAP  134
#define SEQ  144
#define INV  16
#define E_SP 1072
#define E_FT 64
#define NTHR 320
#define XSTR 160
#define YSTR 20   // padded row stride for sYA/sYF (multiple of 4 for float4 reads)

// ---------------- device-global precomputed state (no cudaMalloc allowed) ----
__device__ int    g_rowptr[CAP + 1];
__device__ int    g_col[E_SP];
__device__ float  g_invdeg[CAP];
__device__ float  g_G1[INV][INV];   // Wl @ F1
__device__ float  g_G2[INV][INV];   // Wr @ F1
__device__ float  g_B1[INV][INV];   // A^T @ F2
__device__ float  g_F2[INV][INV];   // F2
__device__ float  g_V[5][INV][INV]; // combined conv taps folded with F3
__device__ float  g_csF2[INV];      // column sums of F2 (for fgcn_bl term)
__device__ float  g_const[INV];     // bl@F1 + fc_b
__device__ float2 g_W2[SEQ * SEQ];  // packed (fWl[t][s], fWr[t][s])

// ---------------- prep kernel: deterministic CSR + folded matrices ----------
// Edge lists staged in shared memory so the per-node scans are LDS loops,
// not serialized L2-latency chains.
__global__ void prep_kernel(const int* __restrict__ gei, const int* __restrict__ fei,
                            const float* __restrict__ Wl, const float* __restrict__ bl,
                            const float* __restrict__ Wr,
                            const float* __restrict__ c1w, const float* __restrict__ c2w,
                            const float* __restrict__ fcw, const float* __restrict__ fcb) {
    int tid = threadIdx.x; // 256 threads
    __shared__ int   s_src[E_SP];
    __shared__ int   s_dst[E_SP];
    __shared__ int   s_deg[CAP];
    __shared__ int   s_cnt[INV][INV];
    __shared__ float s_A[INV][INV];

    for (int e = tid; e < E_SP; e += 256) {
        s_src[e] = gei[e];
        s_dst[e] = gei[E_SP + e];
    }
    __syncthreads();

    if (tid < CAP) {
        int cnt = 0;
        #pragma unroll 8
        for (int e = 0; e < E_SP; e++) if (s_dst[e] == tid) cnt++;
        s_deg[tid] = cnt;
        g_invdeg[tid] = 1.0f / fmaxf((float)cnt, 1.0f);
    }
    __syncthreads();
    if (tid == 0) {
        int acc = 0;
        for (int c = 0; c < CAP; c++) { g_rowptr[c] = acc; acc += s_deg[c]; }
        g_rowptr[CAP] = acc;
    }
    __syncthreads();
    if (tid < CAP) {
        int k = g_rowptr[tid];
        #pragma unroll 8
        for (int e = 0; e < E_SP; e++)
            if (s_dst[e] == tid) g_col[k++] = s_src[e];
    }
    {
        int i = tid >> 4, j = tid & 15;
        int cnt = 0;
        for (int e = 0; e < E_FT; e++)
            if (fei[E_FT + e] == i && fei[e] == j) cnt++;
        s_cnt[i][j] = cnt;
    }
    __syncthreads();
    {
        int i = tid >> 4, j = tid & 15;
        int dsum = 0;
        for (int jj = 0; jj < INV; jj++) dsum += s_cnt[i][jj];
        s_A[i][j] = (float)s_cnt[i][j] / fmaxf((float)dsum, 1.0f);
    }
    __syncthreads();
    {
        int r = tid >> 4, o = tid & 15;
        float g1 = 0.f, g2 = 0.f, b1 = 0.f;
        for (int i = 0; i < INV; i++) {
            float f1 = fcw[i * INV + o];
            float f2 = fcw[(INV + i) * INV + o];
            g1 += Wl[r * INV + i] * f1;
            g2 += Wr[r * INV + i] * f1;
            b1 += s_A[i][r] * f2;
        }
        g_G1[r][o] = g1; g_G2[r][o] = g2; g_B1[r][o] = b1;
        g_F2[r][o] = fcw[(INV + r) * INV + o];
        for (int k = 0; k < 5; k++) {
            float v = 0.f;
            for (int o2 = 0; o2 < INV; o2++) {
                float w5 = c2w[(o2 * INV + r) * 5 + k];
                if (k >= 1 && k <= 3) w5 += c1w[(o2 * INV + r) * 3 + (k - 1)];
                v += w5 * fcw[(32 + o2) * INV + o];
            }
            g_V[k][r][o] = v;
        }
        if (r == 0) {
            float cs = 0.f, cv = 0.f;
            for (int i = 0; i < INV; i++) {
                cs += fcw[(INV + i) * INV + o];
                cv += bl[i] * fcw[i * INV + o];
            }
            g_csF2[o] = cs;
            g_const[o] = cv + fcb[o];
        }
    }
}

// pack (fWl, fWr) into interleaved float2 so the hot loop does 1 LDG.64 not 2 LDG.32
__global__ void w2_kernel(const float* __restrict__ fWl, const float* __restrict__ fWr) {
    int i = blockIdx.x * blockDim.x + threadIdx.x;
    if (i < SEQ * SEQ) g_W2[i] = make_float2(fWl[i], fWr[i]);
}

// ---------------- main fused kernel: one (b,c) slice per block --------------
// 320 threads: s = tid % 160 (seq position), h = tid / 160 (output half).
// Each thread computes 8 of the 16 output channels -> shorter FFMA chains,
// 10 warps/block for latency hiding, lower register pressure.
__global__ __launch_bounds__(NTHR, 4)
void stconv_kernel(const float* __restrict__ src,
                   const float* __restrict__ fbl,
                   float* __restrict__ out) {
    __shared__ __align__(16) float sX[INV][XSTR];      // transposed X: sX[i][s]
    __shared__ __align__(16) float sYA[SEQ][YSTR];     // X @ (A^T F2)
    __shared__ __align__(16) float sYF[SEQ][YSTR];     // X @ F2
    __shared__ __align__(16) float sG1[INV][INV], sG2[INV][INV], sB1[INV][INV], sF2[INV][INV];
    __shared__ __align__(16) float sV[5][INV][INV];
    __shared__ float sCs[INV], sC0[INV];

    const int c = blockIdx.x, b = blockIdx.y;
    const int tid = threadIdx.x;
    const int s  = tid % 160;
    const int h  = tid / 160;      // 0 or 1
    const int ob = h * 8;          // output-channel base for this thread
    const int base = ((b * CAP + c) * SEQ) * INV;

    if (tid < INV * INV) {
        int r = tid >> 4, o = tid & 15;
        sG1[r][o] = g_G1[r][o]; sG2[r][o] = g_G2[r][o];
        sB1[r][o] = g_B1[r][o]; sF2[r][o] = g_F2[r][o];
        #pragma unroll
        for (int k = 0; k < 5; k++) sV[k][r][o] = g_V[k][r][o];
        if (r == 0) { sCs[o] = g_csF2[o]; sC0[o] = g_const[o]; }
    }

    if (h == 0 && s < SEQ) {
        const float4* p = (const float4*)(src + base + s * INV);
        float4 a0 = p[0], a1 = p[1], a2 = p[2], a3 = p[3];
        sX[0][s]=a0.x;  sX[1][s]=a0.y;  sX[2][s]=a0.z;  sX[3][s]=a0.w;
        sX[4][s]=a1.x;  sX[5][s]=a1.y;  sX[6][s]=a1.z;  sX[7][s]=a1.w;
        sX[8][s]=a2.x;  sX[9][s]=a2.y;  sX[10][s]=a2.z; sX[11][s]=a2.w;
        sX[12][s]=a3.x; sX[13][s]=a3.y; sX[14][s]=a3.z; sX[15][s]=a3.w;
    }
    __syncthreads();

    float acc[8];
    if (s < SEQ) {
        // YA/YF half-rows for this (s, h)
        {
            float ya[8], yf[8];
            #pragma unroll
            for (int k = 0; k < 8; k++) { ya[k] = 0.f; yf[k] = 0.f; }
            #pragma unroll
            for (int j = 0; j < 16; j++) {
                float xv = sX[j][s];
                #pragma unroll
                for (int k = 0; k < 8; k++) {
                    ya[k] += xv * sB1[j][ob + k];
                    yf[k] += xv * sF2[j][ob + k];
                }
            }
            #pragma unroll
            for (int k = 0; k < 8; k++) { sYA[s][ob + k] = ya[k]; sYF[s][ob + k] = yf[k]; }
        }

        // constant + fgcn_bl term
        float fblv = __ldg(fbl + s);
        #pragma unroll
        for (int k = 0; k < 8; k++) acc[k] = sC0[ob + k] + fblv * sCs[ob + k];

        // spatial: gather mean over graph neighbors of c
        {
            int r0 = g_rowptr[c], r1 = g_rowptr[c + 1];
            float mg[16];
            #pragma unroll
            for (int o = 0; o < 16; o++) mg[o] = 0.f;
            for (int e = r0; e < r1; e++) {
                int nb = g_col[e];
                const float4* p = (const float4*)(src + ((b * CAP + nb) * SEQ + s) * INV);
                float4 a0 = __ldg(p), a1 = __ldg(p + 1), a2 = __ldg(p + 2), a3 = __ldg(p + 3);
                mg[0]+=a0.x; mg[1]+=a0.y; mg[2]+=a0.z; mg[3]+=a0.w;
                mg[4]+=a1.x; mg[5]+=a1.y; mg[6]+=a1.z; mg[7]+=a1.w;
                mg[8]+=a2.x; mg[9]+=a2.y; mg[10]+=a2.z; mg[11]+=a2.w;
                mg[12]+=a3.x; mg[13]+=a3.y; mg[14]+=a3.z; mg[15]+=a3.w;
            }
            float sc = g_invdeg[c];
            #pragma unroll
            for (int j = 0; j < 16; j++) {
                float m = mg[j] * sc;
                float xv = sX[j][s];
                #pragma unroll
                for (int k = 0; k < 8; k++)
                    acc[k] += m * sG1[j][ob + k] + xv * sG2[j][ob + k];
            }
        }

        // temporal: combined 5-tap conv with F3 folded in
        #pragma unroll
        for (int k5 = 0; k5 < 5; k5++) {
            int sp = s + k5 - 2;
            if (sp >= 0 && sp < SEQ) {
                #pragma unroll
                for (int j = 0; j < 16; j++) {
                    float xv = sX[j][sp];
                    #pragma unroll
                    for (int k = 0; k < 8; k++) acc[k] += xv * sV[k5][j][ob + k];
                }
            }
        }
    }
    __syncthreads();

    if (s < SEQ) {
        // big GEMM: acc += sum_t fWl[t][s]*YA[t][ob:ob+8] + fWr[t][s]*YF[t][ob:ob+8]
        const float2* wp = g_W2 + s;
        const int q = h * 2;
        #pragma unroll 4
        for (int t = 0; t < SEQ; t++) {
            float2 w = wp[t * SEQ];
            float a = w.x, bb = w.y;
            const float4* yap = (const float4*)sYA[t];
            const float4* yfp = (const float4*)sYF[t];
            float4 u0 = yap[q], u1 = yap[q + 1];
            float4 v0 = yfp[q], v1 = yfp[q + 1];
            acc[0] += a*u0.x + bb*v0.x;  acc[1] += a*u0.y + bb*v0.y;
            acc[2] += a*u0.z + bb*v0.z;  acc[3] += a*u0.w + bb*v0.w;
            acc[4] += a*u1.x + bb*v1.x;  acc[5] += a*u1.y + bb*v1.y;
            acc[6] += a*u1.z + bb*v1.z;  acc[7] += a*u1.w + bb*v1.w;
        }

        // out = src + contributions (x re-read from smem)
        float4* po = (float4*)(out + base + s * INV);
        po[q]     = make_float4(sX[ob+0][s]+acc[0], sX[ob+1][s]+acc[1],
                                sX[ob+2][s]+acc[2], sX[ob+3][s]+acc[3]);
        po[q + 1] = make_float4(sX[ob+4][s]+acc[4], sX[ob+5][s]+acc[5],
                                sX[ob+6][s]+acc[6], sX[ob+7][s]+acc[7]);
    }
}

// ---------------- launch ----------------------------------------------------
extern "C" void kernel_launch(void* const* d_in, const int* in_sizes, int n_in,
                              void* d_out, int out_size) {
    const float* src = (const float*)d_in[0];
    const int*   gei = (const int*)d_in[1];
    const int*   fei = (const int*)d_in[2];
    const float* Wl  = (const float*)d_in[3];
    const float* bl  = (const float*)d_in[4];
    const float* Wr  = (const float*)d_in[5];
    const float* fWl = (const float*)d_in[6];
    const float* fbl = (const float*)d_in[7];
    const float* fWr = (const float*)d_in[8];
    const float* c1w = (const float*)d_in[9];
    const float* c2w = (const float*)d_in[10];
    const float* fcw = (const float*)d_in[11];
    const float* fcb = (const float*)d_in[12];

    prep_kernel<<<1, 256>>>(gei, fei, Wl, bl, Wr, c1w, c2w, fcw, fcb);
    w2_kernel<<<(SEQ * SEQ + 255) / 256, 256>>>(fWl, fWr);
    dim3 grid(CAP, BZ);
    stconv_kernel<<<grid, NTHR>>>(src, fbl, (float*)d_out);
}